// round 2
// baseline (speedup 1.0000x reference)
#include <cuda_runtime.h>
#include <cuda_bf16.h>
#include <cstdint>

// Capsule routing: B=2048, R=64, H=512, NUM_ITER=3.  Output final_vec [B,H] f32.
//
// Collapsed algorithm (b_ij accumulates x*v):
//   s0 = mean_r x;               v1 = squash(s0)
//   softmax_r(x * v1)        ->  v2 = squash(sum_r c x)
//   softmax_r(x * (v1+v2))   ->  v3 = squash(sum_r c x)   -> output v3
//
// R2 layout: 1 CTA per batch, 1024 threads. Each h-column (64 rows) is split
// across 2 threads (32 rows each) -> xr[32] regs -> <=64 regs/thread ->
// 32 warps resident/SM (2x occupancy vs R1). Halves exchange partials via
// smem; both compute identical scalars afterwards (commutative adds).

#define B_DIM 2048
#define R_DIM 64
#define H_DIM 512
#define NTHREADS 1024
#define R_HALF 32

__device__ __forceinline__ float fast_exp2(float x) {
    float r;
    asm("ex2.approx.ftz.f32 %0, %1;" : "=f"(r) : "f"(x));
    return r;
}

// Block-wide sum over 1024 threads (32 warps). Returns result to all threads.
__device__ __forceinline__ float block_sum(float val, float* sred) {
    #pragma unroll
    for (int o = 16; o > 0; o >>= 1)
        val += __shfl_xor_sync(0xffffffffu, val, o);
    int wid = threadIdx.x >> 5;
    int lid = threadIdx.x & 31;
    __syncthreads();                 // protect sred reuse across calls
    if (lid == 0) sred[wid] = val;
    __syncthreads();
    if (threadIdx.x < 32) {
        float v = sred[lid];
        #pragma unroll
        for (int o = 16; o > 0; o >>= 1)
            v += __shfl_xor_sync(0xffffffffu, v, o);
        if (lid == 0) sred[0] = v;
    }
    __syncthreads();
    return sred[0];
}

__global__ void __launch_bounds__(NTHREADS, 1)
capsule_kernel(const float* __restrict__ x, float* __restrict__ out) {
    __shared__ float sh_a[NTHREADS];
    __shared__ float sh_b[NTHREADS];
    __shared__ float sh_c[NTHREADS];
    __shared__ float sred[32];

    const int tid  = threadIdx.x;
    const int h    = tid & (H_DIM - 1);
    const int half = tid >> 9;              // 0 or 1: which 32-row half
    const int prt  = tid ^ 512;             // partner thread index
    const int b    = blockIdx.x;

    const float* xb = x + (size_t)b * (R_DIM * H_DIM)
                        + (size_t)(half * R_HALF) * H_DIM + h;

    // ---- load 32 rows; fused partial sum / max / min ----
    float xr[R_HALF];
    float psum = 0.0f;
    float pmax = -3.402823466e38f;
    float pmin =  3.402823466e38f;
    #pragma unroll
    for (int i = 0; i < R_HALF; i++) {
        xr[i] = __ldg(xb + i * H_DIM);
        psum += xr[i];
        pmax = fmaxf(pmax, xr[i]);
        pmin = fminf(pmin, xr[i]);
    }
    sh_a[tid] = psum;
    sh_b[tid] = pmax;
    sh_c[tid] = pmin;
    __syncthreads();
    const float sum0 = psum + sh_a[prt];
    const float xmax = fmaxf(pmax, sh_b[prt]);
    const float xmin = fminf(pmin, sh_c[prt]);

    // ---- iter 0: uniform coefficients -> mean over r, squash ----
    float s = sum0 * (1.0f / (float)R_DIM);
    float norm = block_sum(0.5f * s * s, sred);   // each pair contributes s^2 once
    float sq = sqrtf(norm);
    float f  = sq / (1.0f + sq);
    float v  = f * s;       // v1 component at this h
    float w  = v;           // accumulated routing weight

    const float L2E = 1.4426950408889634f;

    // ---- iterations 1 and 2 ----
    #pragma unroll
    for (int it = 0; it < 2; it++) {
        float wl = w * L2E;
        float m  = fmaxf(wl * xmax, wl * xmin);   // max_r(x_r * wl)
        float pse  = 0.0f;
        float psex = 0.0f;
        #pragma unroll
        for (int i = 0; i < R_HALF; i++) {
            float e = fast_exp2(fmaf(xr[i], wl, -m));
            pse += e;
            psex = fmaf(e, xr[i], psex);
        }
        sh_a[tid] = pse;
        sh_b[tid] = psex;
        __syncthreads();
        float se  = pse  + sh_a[prt];
        float sex = psex + sh_b[prt];
        s = sex / se;                              // sum_r c_r x_r

        norm = block_sum(0.5f * s * s, sred);      // block_sum syncs protect sh_a/sh_b
        sq = sqrtf(norm);
        f  = sq / (1.0f + sq);
        v  = f * s;
        w += v;
    }

    if (half == 0)
        out[(size_t)b * H_DIM + h] = v;
}

extern "C" void kernel_launch(void* const* d_in, const int* in_sizes, int n_in,
                              void* d_out, int out_size) {
    const float* x = (const float*)d_in[0];
    float* out = (float*)d_out;
    capsule_kernel<<<B_DIM, NTHREADS>>>(x, out);
}